// round 7
// baseline (speedup 1.0000x reference)
#include <cuda_runtime.h>
#include <cuda_fp16.h>
#include <math.h>
#include <stdint.h>

// Problem shape (fixed by dataset)
#define BB 2
#define CC 16
#define FP 30
#define FA 50
#define SS 20
#define TT 1024
#define NB 18
#define NBC 19
#define PKA (FP*FA)              // 1500
#define PKAL (PKA/2)             // 750 per half-block

#define THREADS 288              // 9 warps; 2 CTAs co-resident per SM
#define NWARP 9
#define KT 32                    // t per chunk
#define NCH (TT/KT)              // 32 chunks
#define FPL 15                   // p rows per block (half of 30)
#define MROWS_L (FPL*NB)         // 270 used M rows
#define MPAD_L 272               // 17 strips of 16
#define LDA_B 80                 // A row stride bytes (odd*16 -> conflict-free LDSM)
#define LDB_B 80
#define LDH 52                   // hist row stride (floats)

#define A_BUF (MPAD_L*LDA_B)     // 21760
#define B_SUB (64*LDB_B)         // 5120

// ---- SMEM byte layout (per 288-thread CTA) ----
#define OFF_A     0                         // 2 bufs fp16 mask [272][40h] = 43520
#define OFF_B     (2*A_BUF)                 // 4 sub-bufs (buf x {hi,lo})  = 20480
#define OFF_BINS  (OFF_B + 4*B_SUB)         // u32[15][256]                = 15360
#define OFF_CNT   (OFF_BINS + FPL*TT)       // f32[270]                    =  1080
#define OFF_CUT   (OFF_CNT + MROWS_L*4)     // f32[20]
#define OFF_FLAG  (OFF_CUT + 80)
#define SMEM_BYTES (OFF_FLAG + 16)          // 80536 B -> 2 CTAs = 161 KB/SM
// hist overlay (after mainloop): f32[272][52] = 56576 B over A+B (64000) OK

__device__ float    g_scratch[BB*CC*SS*PKA];
__device__ unsigned g_tick[BB*CC];

__device__ __forceinline__ uint32_t smem_u32(const void* p) {
    uint32_t a;
    asm("{ .reg .u64 t; cvta.to.shared.u64 t, %1; cvt.u32.u64 %0, t; }" : "=r"(a) : "l"(p));
    return a;
}
__device__ __forceinline__ void ldm_x4(uint32_t& r0, uint32_t& r1, uint32_t& r2, uint32_t& r3,
                                       uint32_t addr) {
    asm volatile("ldmatrix.sync.aligned.m8n8.x4.shared.b16 {%0,%1,%2,%3}, [%4];"
                 : "=r"(r0), "=r"(r1), "=r"(r2), "=r"(r3) : "r"(addr));
}
__device__ __forceinline__ void ldm_x2(uint32_t& r0, uint32_t& r1, uint32_t addr) {
    asm volatile("ldmatrix.sync.aligned.m8n8.x2.shared.b16 {%0,%1}, [%2];"
                 : "=r"(r0), "=r"(r1) : "r"(addr));
}
__device__ __forceinline__ void mma16816(float* c, uint32_t a0, uint32_t a1, uint32_t a2,
                                         uint32_t a3, uint32_t b0, uint32_t b1) {
    asm volatile("mma.sync.aligned.m16n8k16.row.col.f32.f16.f16.f32 "
                 "{%0,%1,%2,%3}, {%4,%5,%6,%7}, {%8,%9}, {%0,%1,%2,%3};"
                 : "+f"(c[0]), "+f"(c[1]), "+f"(c[2]), "+f"(c[3])
                 : "r"(a0), "r"(a1), "r"(a2), "r"(a3), "r"(b0), "r"(b1));
}

__device__ __forceinline__ int bin_of(float x, const float* __restrict__ cut,
                                      float c0, float inv_step)
{
    // exact searchsorted(side='left'): cnt = #{j: cut[j] < x}; bin = clamp(cnt-1,0,NB-1)
    int g = (int)floorf((x - c0) * inv_step) + 1;
    g = min(max(g, 0), NBC);
    { float cl = cut[max(g-1,0)];   if (g > 0   && cl >= x) g--; }
    { float cl = cut[max(g-1,0)];   if (g > 0   && cl >= x) g--; }
    { float ch = cut[min(g,NBC-1)]; if (g < NBC && ch <  x) g++; }
    { float ch = cut[min(g,NBC-1)]; if (g < NBC && ch <  x) g++; }
    return min(max(g - 1, 0), NB - 1);
}

__global__ __launch_bounds__(THREADS, 2)
void mi_main(const float* __restrict__ pha,
             const float* __restrict__ amp,
             const float* __restrict__ cuts,
             float* __restrict__ out)
{
    extern __shared__ char smraw[];
    const uint32_t smem_base = smem_u32(smraw);
    uint32_t* bins32 = (uint32_t*)(smraw + OFF_BINS);   // [15][256]
    float*    cnt    = (float*)(smraw + OFF_CNT);       // [270]
    float*    cut    = (float*)(smraw + OFF_CUT);
    int*      sflag  = (int*)(smraw + OFF_FLAG);

    const int tid  = threadIdx.x;
    const int wid  = tid >> 5;
    const int lane = tid & 31;
    const int bid  = blockIdx.x;     // (bc*SS + s)*2 + half
    const int half = bid & 1;
    const int sidx = bid >> 1;
    const int s    = sidx % SS;
    const int bc   = sidx / SS;
    const unsigned FULL = 0xFFFFFFFFu;

    // ---- phase 0: zero A + B buffers, load cutoffs ----
    for (int i = tid; i < OFF_BINS/16; i += THREADS)
        ((float4*)smraw)[i] = make_float4(0.f, 0.f, 0.f, 0.f);
    if (tid < NBC) cut[tid] = cuts[tid];
    __syncthreads();

    const float c0       = cut[0];
    const float inv_step = (float)NB / (cut[NB] - c0);

    // ---- phase 1: bin this half's 15 pha rows; per-(p,k) counts ----
    for (int p = wid; p < FPL; p += NWARP) {
        const int pg = half*FPL + p;
        const float4* prow = (const float4*)(pha + ((size_t)(bc*FP + pg)*SS + s)*(size_t)TT);
        int ctot = 0;
        #pragma unroll
        for (int it = 0; it < 8; ++it) {
            float4 v = prow[it*32 + lane];
            int b0 = bin_of(v.x, cut, c0, inv_step);
            int b1 = bin_of(v.y, cut, c0, inv_step);
            int b2 = bin_of(v.z, cut, c0, inv_step);
            int b3 = bin_of(v.w, cut, c0, inv_step);
            bins32[p*256 + it*32 + lane] =
                (unsigned)b0 | ((unsigned)b1 << 8) | ((unsigned)b2 << 16) | ((unsigned)b3 << 24);
            unsigned long long pc0 = 0, pc1 = 0, pc2 = 0;
            int bb[4] = {b0, b1, b2, b3};
            #pragma unroll
            for (int j = 0; j < 4; ++j) {
                int w = bb[j] >> 3;
                unsigned long long one = 1ULL << ((bb[j] & 7) * 8);
                if (w == 0) pc0 += one; else if (w == 1) pc1 += one; else pc2 += one;
            }
            #pragma unroll
            for (int d = 16; d >= 1; d >>= 1) {
                pc0 += __shfl_xor_sync(FULL, pc0, d);
                pc1 += __shfl_xor_sync(FULL, pc1, d);
                pc2 += __shfl_xor_sync(FULL, pc2, d);
            }
            if (lane < NB) {
                int w = lane >> 3;
                unsigned long long tw = (w == 0) ? pc0 : (w == 1) ? pc1 : pc2;
                ctot += (int)((tw >> ((lane & 7) * 8)) & 0xFF);
            }
        }
        if (lane < NB) cnt[p*NB + lane] = (float)ctot;
    }
    __syncthreads();

    // ---- phase 2: pipelined mask-GEMM mainloop (HMMA, double-buffered) ----
    const size_t ampOff = ((size_t)bc*FA*SS + s)*(size_t)TT;
    float acc[2][8][4] = {};
    const int  nstrips = (wid < 8) ? 2 : 1;

    // B work items: 400 = 50 a-rows x 8 float4; thread handles tid and tid+288
    const int  pa0 = tid >> 3,        pj0 = tid & 7;
    const int  i1  = tid + THREADS;
    const int  pa1 = i1 >> 3,         pj1 = i1 & 7;
    const bool act1 = (i1 < FA*(KT/4));          // 400
    const float* pSrc0 = amp + ampOff + (size_t)pa0*SS*TT + pj0*4;
    const float* pSrc1 = amp + ampOff + (size_t)pa1*SS*TT + pj1*4;

    float4 vpre0 = *(const float4*)(pSrc0);
    float4 vpre1 = act1 ? *(const float4*)(pSrc1) : make_float4(0,0,0,0);

    for (int c = 0; c < NCH; ++c) {
        const int buf = c & 1;

        // -- build B from prefetched registers: hi/lo fp16 split --
        {
            char* Bh = smraw + OFF_B + (buf*2 + 0)*B_SUB;
            char* Bl = smraw + OFF_B + (buf*2 + 1)*B_SUB;
            #pragma unroll
            for (int r = 0; r < 2; ++r) {
                if (r == 1 && !act1) break;
                float4 v  = r ? vpre1 : vpre0;
                int    pa = r ? pa1 : pa0;
                int    pj = r ? pj1 : pj0;
                __half h0 = __float2half_rn(v.x), h1 = __float2half_rn(v.y);
                __half h2 = __float2half_rn(v.z), h3 = __float2half_rn(v.w);
                __half l0 = __float2half_rn(v.x - __half2float(h0));
                __half l1 = __float2half_rn(v.y - __half2float(h1));
                __half l2 = __float2half_rn(v.z - __half2float(h2));
                __half l3 = __float2half_rn(v.w - __half2float(h3));
                uint2 ph, pl;
                ph.x = (uint32_t)__half_as_ushort(h0) | ((uint32_t)__half_as_ushort(h1) << 16);
                ph.y = (uint32_t)__half_as_ushort(h2) | ((uint32_t)__half_as_ushort(h3) << 16);
                pl.x = (uint32_t)__half_as_ushort(l0) | ((uint32_t)__half_as_ushort(l1) << 16);
                pl.y = (uint32_t)__half_as_ushort(l2) | ((uint32_t)__half_as_ushort(l3) << 16);
                *(uint2*)(Bh + pa*LDB_B + pj*8) = ph;
                *(uint2*)(Bl + pa*LDB_B + pj*8) = pl;
            }
            // prefetch next chunk early (hidden under this chunk's MMAs)
            if (c + 1 < NCH) {
                vpre0 = *(const float4*)(pSrc0 + (c + 1)*KT);
                if (act1) vpre1 = *(const float4*)(pSrc1 + (c + 1)*KT);
            }
        }
        // -- build A mask into buf: clear chunk c-2 ones, set chunk c ones --
        if (tid < FPL*(KT/4)) {                  // 120 items
            char* Ab = smraw + OFF_A + buf*A_BUF;
            int p = tid >> 3, tq = tid & 7;
            int tl = tq * 4;
            if (c >= 2) {
                unsigned w = bins32[p*256 + (c-2)*8 + tq];
                #pragma unroll
                for (int j = 0; j < 4; ++j) {
                    int row = p*NB + ((w >> (8*j)) & 0xFF);
                    *(uint16_t*)(Ab + row*LDA_B + (tl + j)*2) = 0;
                }
            }
            {
                unsigned w = bins32[p*256 + c*8 + tq];
                #pragma unroll
                for (int j = 0; j < 4; ++j) {
                    int row = p*NB + ((w >> (8*j)) & 0xFF);
                    *(uint16_t*)(Ab + row*LDA_B + (tl + j)*2) = 0x3C00;  // fp16 1.0
                }
            }
        }
        __syncthreads();

        // -- MMA on buf: 2 ksteps x 2 splits x (strips x 8 ntiles) --
        uint32_t Abase = smem_base + OFF_A + buf*A_BUF;
        #pragma unroll
        for (int ks = 0; ks < KT/16; ++ks) {
            uint32_t a0[2], a1[2], a2[2], a3[2];
            #pragma unroll
            for (int s3 = 0; s3 < 2; ++s3) {
                if (s3 >= nstrips) break;
                int strip = (wid < 8) ? (2*wid + s3) : 16;
                uint32_t ad = Abase + (strip*16 + (lane & 15))*LDA_B
                            + ks*32 + (lane >> 4)*16;
                ldm_x4(a0[s3], a1[s3], a2[s3], a3[s3], ad);
            }
            #pragma unroll
            for (int sp = 0; sp < 2; ++sp) {
                uint32_t bbase = smem_base + OFF_B + (buf*2 + sp)*B_SUB;
                uint32_t b0[8], b1[8];
                #pragma unroll
                for (int nt = 0; nt < 8; ++nt) {
                    uint32_t bd = bbase + (nt*8 + (lane & 7))*LDB_B
                                + ks*32 + ((lane >> 3) & 1)*16;
                    ldm_x2(b0[nt], b1[nt], bd);
                }
                #pragma unroll
                for (int s3 = 0; s3 < 2; ++s3) {
                    if (s3 >= nstrips) break;
                    #pragma unroll
                    for (int nt = 0; nt < 8; ++nt)
                        mma16816(acc[s3][nt], a0[s3], a1[s3], a2[s3], a3[s3],
                                 b0[nt], b1[nt]);
                }
            }
        }
        // no second sync: next build writes the OTHER buffer
    }
    __syncthreads();   // all MMAs done before hist overlays A region

    // ---- phase 3: accumulators -> SMEM hist[272][52] (overlay A+B region) ----
    float* hist = (float*)smraw;
    #pragma unroll
    for (int s3 = 0; s3 < 2; ++s3) {
        if (s3 >= nstrips) break;
        int strip = (wid < 8) ? (2*wid + s3) : 16;
        int row0  = strip*16 + (lane >> 2);
        #pragma unroll
        for (int nt = 0; nt < 8; ++nt) {
            int n0 = nt*8 + (lane & 3)*2;
            if (n0 < FA) {
                if (row0 < MROWS_L)
                    *(float2*)&hist[row0*LDH + n0] = make_float2(acc[s3][nt][0], acc[s3][nt][1]);
                if (row0 + 8 < MROWS_L)
                    *(float2*)&hist[(row0+8)*LDH + n0] = make_float2(acc[s3][nt][2], acc[s3][nt][3]);
            }
        }
    }
    __syncthreads();

    // ---- phase 4: entropy -> MI per (p,a) for this half ----
    const float eps  = 1e-9f;
    const float LN18 = 2.8903717578961645f;
    for (int task = tid; task < PKAL; task += THREADS) {
        int p = task / FA;
        int a = task - p*FA;
        float m[NB];
        float msum = 0.0f;
        #pragma unroll
        for (int k = 0; k < NB; ++k) {
            m[k] = hist[(p*NB + k)*LDH + a] / (cnt[p*NB + k] + eps);
            msum += m[k];
        }
        float inv = 1.0f / (msum + eps);
        float ent = 0.0f;
        #pragma unroll
        for (int k = 0; k < NB; ++k) {
            float pr = m[k] * inv;
            ent += pr * logf(pr + eps);
        }
        g_scratch[((size_t)bc*SS + s)*PKA + half*PKAL + task] = (LN18 + ent) * (1.0f / LN18);
    }

    // ---- phase 5: last block per bc (of 2*SS) reduces over s ----
    __threadfence();
    __syncthreads();
    if (tid == 0) {
        unsigned old = atomicAdd(&g_tick[bc], 1u);
        *sflag = (old == 2*SS - 1) ? 1 : 0;
    }
    __syncthreads();
    if (*sflag) {
        __threadfence();
        for (int i = tid; i < PKA; i += THREADS) {
            float acc2 = 0.0f;
            #pragma unroll
            for (int ss2 = 0; ss2 < SS; ++ss2)
                acc2 += g_scratch[((size_t)bc*SS + ss2)*PKA + i];
            out[(size_t)bc*PKA + i] = acc2 * (1.0f / (float)SS);
        }
        __syncthreads();
        if (tid == 0) g_tick[bc] = 0;   // net-zero for graph replay
    }
}

extern "C" void kernel_launch(void* const* d_in, const int* in_sizes, int n_in,
                              void* d_out, int out_size)
{
    const float* pha  = (const float*)d_in[0];
    const float* amp  = (const float*)d_in[1];
    const float* cuts = (const float*)d_in[2];
    float* out = (float*)d_out;

    cudaFuncSetAttribute(mi_main, cudaFuncAttributeMaxDynamicSharedMemorySize, SMEM_BYTES);
    mi_main<<<BB*CC*SS*2, THREADS, SMEM_BYTES>>>(pha, amp, cuts, out);
}

// round 10
// speedup vs baseline: 1.2308x; 1.2308x over previous
#include <cuda_runtime.h>
#include <cuda_fp16.h>
#include <math.h>
#include <stdint.h>

// Problem shape (fixed by dataset)
#define BB 2
#define CC 16
#define FP 30
#define FA 50
#define SS 20
#define TT 1024
#define NB 18
#define NBC 19
#define PKA (FP*FA)              // 1500
#define PKAL (PKA/2)             // 750 per half-block

#define THREADS 544              // 17 warps; 2 CTAs co-resident per SM
#define NWARP 17
#define KT 32                    // t per chunk
#define NCH (TT/KT)              // 32 chunks
#define FPL 15                   // p rows per block (half of 30)
#define MROWS_L (FPL*NB)         // 270 used M rows
#define MPAD_L 272               // 17 strips of 16, 1 per warp
#define NTILE 7                  // n tiles (56 >= 50)
#define LDA_B 80                 // A row stride bytes (odd*16 -> conflict-free LDSM)
#define LDB_B 80
#define LDH 52                   // hist row stride (floats)

#define A_BUF (MPAD_L*LDA_B)     // 21760
#define B_SUB (64*LDB_B)         // 5120

// ---- SMEM byte layout (per CTA) ----
#define OFF_A     0                         // 2 bufs fp16 mask [272][40h] = 43520
#define OFF_B     (2*A_BUF)                 // 4 sub-bufs (buf x {hi,lo})  = 20480
#define OFF_BINS  (OFF_B + 4*B_SUB)         // u32[15][256]                = 15360
#define OFF_CNT   (OFF_BINS + FPL*TT)       // f32[270]                    =  1080
#define OFF_CUT   (OFF_CNT + MROWS_L*4)     // f32[20]
#define OFF_FLAG  (OFF_CUT + 80)
#define SMEM_BYTES (OFF_FLAG + 16)          // 80536 B -> 2 CTAs = 161 KB/SM
// hist overlay (after mainloop): f32[272][52] = 56576 B over A+B (64000) OK

__device__ float    g_scratch[BB*CC*SS*PKA];
__device__ unsigned g_tick[BB*CC];

__device__ __forceinline__ uint32_t smem_u32(const void* p) {
    uint32_t a;
    asm("{ .reg .u64 t; cvta.to.shared.u64 t, %1; cvt.u32.u64 %0, t; }" : "=r"(a) : "l"(p));
    return a;
}
__device__ __forceinline__ void ldm_x4(uint32_t& r0, uint32_t& r1, uint32_t& r2, uint32_t& r3,
                                       uint32_t addr) {
    asm volatile("ldmatrix.sync.aligned.m8n8.x4.shared.b16 {%0,%1,%2,%3}, [%4];"
                 : "=r"(r0), "=r"(r1), "=r"(r2), "=r"(r3) : "r"(addr));
}
__device__ __forceinline__ void ldm_x2(uint32_t& r0, uint32_t& r1, uint32_t addr) {
    asm volatile("ldmatrix.sync.aligned.m8n8.x2.shared.b16 {%0,%1}, [%2];"
                 : "=r"(r0), "=r"(r1) : "r"(addr));
}
__device__ __forceinline__ void mma16816(float* c, uint32_t a0, uint32_t a1, uint32_t a2,
                                         uint32_t a3, uint32_t b0, uint32_t b1) {
    asm volatile("mma.sync.aligned.m16n8k16.row.col.f32.f16.f16.f32 "
                 "{%0,%1,%2,%3}, {%4,%5,%6,%7}, {%8,%9}, {%0,%1,%2,%3};"
                 : "+f"(c[0]), "+f"(c[1]), "+f"(c[2]), "+f"(c[3])
                 : "r"(a0), "r"(a1), "r"(a2), "r"(a3), "r"(b0), "r"(b1));
}

__device__ __forceinline__ int bin_of(float x, const float* __restrict__ cut,
                                      float c0, float inv_step)
{
    // exact searchsorted(side='left'): cnt = #{j: cut[j] < x}; bin = clamp(cnt-1,0,NB-1)
    int g = (int)floorf((x - c0) * inv_step) + 1;
    g = min(max(g, 0), NBC);
    { float cl = cut[max(g-1,0)];   if (g > 0   && cl >= x) g--; }
    { float cl = cut[max(g-1,0)];   if (g > 0   && cl >= x) g--; }
    { float ch = cut[min(g,NBC-1)]; if (g < NBC && ch <  x) g++; }
    { float ch = cut[min(g,NBC-1)]; if (g < NBC && ch <  x) g++; }
    return min(max(g - 1, 0), NB - 1);
}

__global__ __launch_bounds__(THREADS, 2)
void mi_main(const float* __restrict__ pha,
             const float* __restrict__ amp,
             const float* __restrict__ cuts,
             float* __restrict__ out)
{
    extern __shared__ char smraw[];
    const uint32_t smem_base = smem_u32(smraw);
    uint32_t* bins32 = (uint32_t*)(smraw + OFF_BINS);   // [15][256]
    float*    cnt    = (float*)(smraw + OFF_CNT);       // [270]
    float*    cut    = (float*)(smraw + OFF_CUT);
    int*      sflag  = (int*)(smraw + OFF_FLAG);

    const int tid  = threadIdx.x;
    const int wid  = tid >> 5;
    const int lane = tid & 31;
    const int bid  = blockIdx.x;     // (bc*SS + s)*2 + half
    const int half = bid & 1;
    const int sidx = bid >> 1;
    const int s    = sidx % SS;
    const int bc   = sidx / SS;
    const unsigned FULL = 0xFFFFFFFFu;

    // ---- phase 0: zero A + B buffers, load cutoffs ----
    for (int i = tid; i < OFF_BINS/16; i += THREADS)
        ((float4*)smraw)[i] = make_float4(0.f, 0.f, 0.f, 0.f);
    if (tid < NBC) cut[tid] = cuts[tid];
    __syncthreads();

    const float c0       = cut[0];
    const float inv_step = (float)NB / (cut[NB] - c0);

    // ---- phase 1: bin this half's 15 pha rows; per-(p,k) counts ----
    if (wid < FPL) {
        const int p  = wid;
        const int pg = half*FPL + p;
        const float4* prow = (const float4*)(pha + ((size_t)(bc*FP + pg)*SS + s)*(size_t)TT);
        int ctot = 0;
        #pragma unroll
        for (int it = 0; it < 8; ++it) {
            float4 v = prow[it*32 + lane];
            int b0 = bin_of(v.x, cut, c0, inv_step);
            int b1 = bin_of(v.y, cut, c0, inv_step);
            int b2 = bin_of(v.z, cut, c0, inv_step);
            int b3 = bin_of(v.w, cut, c0, inv_step);
            bins32[p*256 + it*32 + lane] =
                (unsigned)b0 | ((unsigned)b1 << 8) | ((unsigned)b2 << 16) | ((unsigned)b3 << 24);
            unsigned long long pc0 = 0, pc1 = 0, pc2 = 0;
            int bb[4] = {b0, b1, b2, b3};
            #pragma unroll
            for (int j = 0; j < 4; ++j) {
                int w = bb[j] >> 3;
                unsigned long long one = 1ULL << ((bb[j] & 7) * 8);
                if (w == 0) pc0 += one; else if (w == 1) pc1 += one; else pc2 += one;
            }
            #pragma unroll
            for (int d = 16; d >= 1; d >>= 1) {
                pc0 += __shfl_xor_sync(FULL, pc0, d);
                pc1 += __shfl_xor_sync(FULL, pc1, d);
                pc2 += __shfl_xor_sync(FULL, pc2, d);
            }
            if (lane < NB) {
                int w = lane >> 3;
                unsigned long long tw = (w == 0) ? pc0 : (w == 1) ? pc1 : pc2;
                ctot += (int)((tw >> ((lane & 7) * 8)) & 0xFF);
            }
        }
        if (lane < NB) cnt[p*NB + lane] = (float)ctot;
    }
    __syncthreads();

    // ---- phase 2: pipelined mask-GEMM mainloop (HMMA, double-buffered) ----
    const size_t ampOff = ((size_t)bc*FA*SS + s)*(size_t)TT;
    float acc[NTILE][4] = {};

    // B work item (1 per thread): 400 items = 50 a-rows x 8 float4
    const int  pa   = tid >> 3;          // a row
    const int  pj   = tid & 7;           // float4 index within KT=32
    const bool pact = (tid < FA*(KT/4)); // 400
    const float* pSrc = amp + ampOff + (size_t)pa*SS*TT + pj*4;

    float4 vpre;
    if (pact) vpre = *(const float4*)(pSrc);   // prefetch chunk 0

    for (int c = 0; c < NCH; ++c) {
        const int buf = c & 1;

        // -- build B from prefetched registers: hi/lo fp16 split --
        if (pact) {
            float4 v = vpre;
            __half h0 = __float2half_rn(v.x), h1 = __float2half_rn(v.y);
            __half h2 = __float2half_rn(v.z), h3 = __float2half_rn(v.w);
            __half l0 = __float2half_rn(v.x - __half2float(h0));
            __half l1 = __float2half_rn(v.y - __half2float(h1));
            __half l2 = __float2half_rn(v.z - __half2float(h2));
            __half l3 = __float2half_rn(v.w - __half2float(h3));
            uint2 ph, pl;
            ph.x = (uint32_t)__half_as_ushort(h0) | ((uint32_t)__half_as_ushort(h1) << 16);
            ph.y = (uint32_t)__half_as_ushort(h2) | ((uint32_t)__half_as_ushort(h3) << 16);
            pl.x = (uint32_t)__half_as_ushort(l0) | ((uint32_t)__half_as_ushort(l1) << 16);
            pl.y = (uint32_t)__half_as_ushort(l2) | ((uint32_t)__half_as_ushort(l3) << 16);
            *(uint2*)(smraw + OFF_B + (buf*2 + 0)*B_SUB + pa*LDB_B + pj*8) = ph;
            *(uint2*)(smraw + OFF_B + (buf*2 + 1)*B_SUB + pa*LDB_B + pj*8) = pl;
            if (c + 1 < NCH) vpre = *(const float4*)(pSrc + (c + 1)*KT);  // hide LDG
        }
        // -- build A mask into buf: clear chunk c-2 ones, set chunk c ones --
        if (tid < FPL*(KT/4)) {                  // 120 items
            char* Ab = smraw + OFF_A + buf*A_BUF;
            int p = tid >> 3, tq = tid & 7;
            int tl = tq * 4;
            if (c >= 2) {
                unsigned w = bins32[p*256 + (c-2)*8 + tq];
                #pragma unroll
                for (int j = 0; j < 4; ++j) {
                    int row = p*NB + ((w >> (8*j)) & 0xFF);
                    *(uint16_t*)(Ab + row*LDA_B + (tl + j)*2) = 0;
                }
            }
            {
                unsigned w = bins32[p*256 + c*8 + tq];
                #pragma unroll
                for (int j = 0; j < 4; ++j) {
                    int row = p*NB + ((w >> (8*j)) & 0xFF);
                    *(uint16_t*)(Ab + row*LDA_B + (tl + j)*2) = 0x3C00;  // fp16 1.0
                }
            }
        }
        __syncthreads();

        // -- MMA on buf: 2 ksteps x 2 splits x (1 strip x 7 ntiles) --
        uint32_t Abase = smem_base + OFF_A + buf*A_BUF;
        #pragma unroll
        for (int ks = 0; ks < KT/16; ++ks) {
            uint32_t a0, a1, a2, a3;
            {
                uint32_t ad = Abase + (wid*16 + (lane & 15))*LDA_B
                            + ks*32 + (lane >> 4)*16;
                ldm_x4(a0, a1, a2, a3, ad);
            }
            #pragma unroll
            for (int sp = 0; sp < 2; ++sp) {
                uint32_t bbase = smem_base + OFF_B + (buf*2 + sp)*B_SUB
                               + ks*32 + ((lane >> 3) & 1)*16;
                uint32_t b0[NTILE], b1[NTILE];
                // nt pairs via ldm_x4: rows ntp*16 + (lane&7) + ((lane>>4)&1)*8
                #pragma unroll
                for (int ntp = 0; ntp < 3; ++ntp) {
                    uint32_t bd = bbase
                                + (ntp*16 + (lane & 7) + ((lane >> 4) & 1)*8)*LDB_B;
                    ldm_x4(b0[2*ntp], b1[2*ntp], b0[2*ntp+1], b1[2*ntp+1], bd);
                }
                {   // nt 6 via ldm_x2
                    uint32_t bd = bbase + (6*8 + (lane & 7))*LDB_B;
                    ldm_x2(b0[6], b1[6], bd);
                }
                #pragma unroll
                for (int nt = 0; nt < NTILE; ++nt)
                    mma16816(acc[nt], a0, a1, a2, a3, b0[nt], b1[nt]);
            }
        }
        // no second sync: next build writes the OTHER buffer
    }
    __syncthreads();   // all MMAs done before hist overlays A region

    // ---- phase 3: accumulators -> SMEM hist[272][52] (overlay A+B region) ----
    float* hist = (float*)smraw;
    {
        int row0 = wid*16 + (lane >> 2);
        #pragma unroll
        for (int nt = 0; nt < NTILE; ++nt) {
            int n0 = nt*8 + (lane & 3)*2;
            if (n0 < FA) {
                if (row0 < MROWS_L)
                    *(float2*)&hist[row0*LDH + n0] = make_float2(acc[nt][0], acc[nt][1]);
                if (row0 + 8 < MROWS_L)
                    *(float2*)&hist[(row0+8)*LDH + n0] = make_float2(acc[nt][2], acc[nt][3]);
            }
        }
    }
    __syncthreads();

    // ---- phase 4: entropy -> MI per (p,a) for this half ----
    const float eps  = 1e-9f;
    const float LN18 = 2.8903717578961645f;
    for (int task = tid; task < PKAL; task += THREADS) {
        int p = task / FA;
        int a = task - p*FA;
        float m[NB];
        float msum = 0.0f;
        #pragma unroll
        for (int k = 0; k < NB; ++k) {
            m[k] = hist[(p*NB + k)*LDH + a] / (cnt[p*NB + k] + eps);
            msum += m[k];
        }
        float inv = 1.0f / (msum + eps);
        float ent = 0.0f;
        #pragma unroll
        for (int k = 0; k < NB; ++k) {
            float pr = m[k] * inv;
            ent += pr * logf(pr + eps);
        }
        g_scratch[((size_t)bc*SS + s)*PKA + half*PKAL + task] = (LN18 + ent) * (1.0f / LN18);
    }

    // ---- phase 5: last block per bc (of 2*SS) reduces over s ----
    __threadfence();
    __syncthreads();
    if (tid == 0) {
        unsigned old = atomicAdd(&g_tick[bc], 1u);
        *sflag = (old == 2*SS - 1) ? 1 : 0;
    }
    __syncthreads();
    if (*sflag) {
        __threadfence();
        for (int i = tid; i < PKA; i += THREADS) {
            float acc2 = 0.0f;
            #pragma unroll
            for (int ss2 = 0; ss2 < SS; ++ss2)
                acc2 += g_scratch[((size_t)bc*SS + ss2)*PKA + i];
            out[(size_t)bc*PKA + i] = acc2 * (1.0f / (float)SS);
        }
        __syncthreads();
        if (tid == 0) g_tick[bc] = 0;   // net-zero for graph replay
    }
}

extern "C" void kernel_launch(void* const* d_in, const int* in_sizes, int n_in,
                              void* d_out, int out_size)
{
    const float* pha  = (const float*)d_in[0];
    const float* amp  = (const float*)d_in[1];
    const float* cuts = (const float*)d_in[2];
    float* out = (float*)d_out;

    cudaFuncSetAttribute(mi_main, cudaFuncAttributeMaxDynamicSharedMemorySize, SMEM_BYTES);
    mi_main<<<BB*CC*SS*2, THREADS, SMEM_BYTES>>>(pha, amp, cuts, out);
}